// round 7
// baseline (speedup 1.0000x reference)
#include <cuda_runtime.h>

#define BB 8
#define SS 2048
#define DD 768
#define NSP 512
#define MAXW 30
#define HH 100
#define M_TOTAL (BB*NSP)   /* 4096 */
#define KSPLIT 4
#define KQ (DD/KSPLIT)     /* 192 */

__device__ float g_logits[BB*SS];
__device__ float g_att[(size_t)M_TOTAL*DD];
__device__ float g_part[(size_t)KSPLIT*M_TOTAL*HH];

__device__ __forceinline__ void f32x2_fma(unsigned long long& acc,
                                          unsigned long long a, unsigned long long b) {
    asm("fma.rn.f32x2 %0, %1, %2, %0;" : "+l"(acc) : "l"(a), "l"(b));
}
__device__ __forceinline__ unsigned long long f32x2_pack(float x, float y) {
    unsigned long long r;
    asm("mov.b64 %0, {%1, %2};" : "=l"(r) : "r"(__float_as_uint(x)), "r"(__float_as_uint(y)));
    return r;
}
__device__ __forceinline__ float2 f32x2_unpack(unsigned long long v) {
    unsigned int lo, hi;
    asm("mov.b64 {%0, %1}, %2;" : "=r"(lo), "=r"(hi) : "l"(v));
    return make_float2(__uint_as_float(lo), __uint_as_float(hi));
}

// ---------------- Kernel 1: logits, 4 rows/warp, f32x2, 2 staged batches -------
// grid = 512, block = 256 (8 warps x 4 rows = 32 rows/block)
__global__ void __launch_bounds__(256, 2) k_logits(const float* __restrict__ seq,
                                                   const float* __restrict__ att_w,
                                                   const float* __restrict__ att_b) {
    __shared__ float sw[DD];
    int tid = threadIdx.x;
    for (int i = tid; i < DD; i += 256) sw[i] = att_w[i];
    __syncthreads();
    int warp = tid >> 5, lane = tid & 31;

    float4 wreg[6];
    const float4* w4 = (const float4*)sw;
#pragma unroll
    for (int j = 0; j < 6; j++) wreg[j] = w4[lane + 32 * j];

    int p0 = (blockIdx.x * 8 + warp) * 4;
    const float4* r0 = (const float4*)(seq + (size_t)(p0 + 0) * DD);
    const float4* r1 = (const float4*)(seq + (size_t)(p0 + 1) * DD);
    const float4* r2 = (const float4*)(seq + (size_t)(p0 + 2) * DD);
    const float4* r3 = (const float4*)(seq + (size_t)(p0 + 3) * DD);

    unsigned long long acc[4] = {0ull, 0ull, 0ull, 0ull};

#pragma unroll
    for (int s = 0; s < 2; s++) {
        float4 x[4][3];
#pragma unroll
        for (int j = 0; j < 3; j++) {
            int col = lane + 32 * (3 * s + j);
            x[0][j] = r0[col]; x[1][j] = r1[col]; x[2][j] = r2[col]; x[3][j] = r3[col];
        }
#pragma unroll
        for (int j = 0; j < 3; j++) {
            const unsigned long long* wp = (const unsigned long long*)&wreg[3 * s + j];
#pragma unroll
            for (int r = 0; r < 4; r++) {
                const unsigned long long* xp = (const unsigned long long*)&x[r][j];
                f32x2_fma(acc[r], xp[0], wp[0]);
                f32x2_fma(acc[r], xp[1], wp[1]);
            }
        }
    }

    float s0, s1, s2, s3;
    { float2 p = f32x2_unpack(acc[0]); s0 = p.x + p.y; }
    { float2 p = f32x2_unpack(acc[1]); s1 = p.x + p.y; }
    { float2 p = f32x2_unpack(acc[2]); s2 = p.x + p.y; }
    { float2 p = f32x2_unpack(acc[3]); s3 = p.x + p.y; }
#pragma unroll
    for (int o = 16; o > 0; o >>= 1) {
        s0 += __shfl_xor_sync(0xffffffffu, s0, o);
        s1 += __shfl_xor_sync(0xffffffffu, s1, o);
        s2 += __shfl_xor_sync(0xffffffffu, s2, o);
        s3 += __shfl_xor_sync(0xffffffffu, s3, o);
    }
    if (lane == 0) {
        float b = att_b[0];
        *(float4*)&g_logits[p0] = make_float4(s0 + b, s1 + b, s2 + b, s3 + b);
    }
}

// ---------------- Kernel 2: per-span softmax + weighted sum (seq L2-hot) -------
__global__ void k_span(const float* __restrict__ seq,
                       const int* __restrict__ spans,
                       const int* __restrict__ mask) {
    __shared__ float s_attn[MAXW];
    __shared__ int   s_start, s_cnt;
    int sp  = blockIdx.x;
    int b   = sp >> 9;
    int tid = threadIdx.x;

    if (tid < 32) {
        int start = spans[sp * 2];
        int cnt   = spans[sp * 2 + 1] - start;        // width 1..30
        float lg = (tid < cnt) ? g_logits[b * SS + start + tid] : -1e30f;
        float mx = lg;
#pragma unroll
        for (int o = 16; o > 0; o >>= 1) mx = fmaxf(mx, __shfl_xor_sync(0xffffffffu, mx, o));
        float ex = (tid < cnt) ? expf(lg - mx) : 0.f;
        float sm = ex;
#pragma unroll
        for (int o = 16; o > 0; o >>= 1) sm += __shfl_xor_sync(0xffffffffu, sm, o);
        float mk = (float)mask[sp];
        if (tid < MAXW) s_attn[tid] = ex / sm * mk;
        if (tid == 0) { s_start = start; s_cnt = cnt; }
    }
    __syncthreads();

    int start = s_start, cnt = s_cnt;
    const float4* base = (const float4*)seq + (size_t)(b * SS + start) * (DD / 4) + tid;
    float4 acc = make_float4(0.f, 0.f, 0.f, 0.f);
#pragma unroll 4
    for (int w = 0; w < cnt; w++) {
        float a  = s_attn[w];
        float4 v = base[(size_t)w * (DD / 4)];
        acc.x += a * v.x; acc.y += a * v.y; acc.z += a * v.z; acc.w += a * v.w;
    }
    ((float4*)g_att)[(size_t)sp * (DD / 4) + tid] = acc;
}

// -------- Kernel 3: GEMM partials, grid-level split-K=4 ------------------------
// grid = (128 M-blocks, 4 K-quarters), block 224 (200 active, 4x4 f32x2 tiles)
#define KC 32
#define NA_F4 ((32*KC)/4)    /* 256 */
#define NW_F4 ((KC*HH)/4)    /* 800 */

__global__ void __launch_bounds__(224) k_gemm(const float* __restrict__ W) {
    __shared__ float sA[KC][36];
    __shared__ float sW[KC][100];

    int m0  = blockIdx.x * 32;
    int kb  = blockIdx.y * KQ;
    int tid = threadIdx.x;

    int ai0 = tid, ai1 = tid + 224;
    int wi0 = tid, wi1 = tid + 224, wi2 = tid + 448, wi3 = tid + 672;

    float4 ra0, ra1, rw0, rw1, rw2, rw3;
    const float4* A4 = (const float4*)g_att;
    const float4* W4 = (const float4*)W;

    {
        int k0 = kb;
        if (ai0 < NA_F4) { int r = ai0 >> 3, kf = ai0 & 7; ra0 = A4[(size_t)(m0 + r) * (DD/4) + (k0>>2) + kf]; }
        if (ai1 < NA_F4) { int r = ai1 >> 3, kf = ai1 & 7; ra1 = A4[(size_t)(m0 + r) * (DD/4) + (k0>>2) + kf]; }
        if (wi0 < NW_F4) { int kk = wi0 / 25, c = wi0 % 25; rw0 = W4[(size_t)(k0 + kk) * (HH/4) + c]; }
        if (wi1 < NW_F4) { int kk = wi1 / 25, c = wi1 % 25; rw1 = W4[(size_t)(k0 + kk) * (HH/4) + c]; }
        if (wi2 < NW_F4) { int kk = wi2 / 25, c = wi2 % 25; rw2 = W4[(size_t)(k0 + kk) * (HH/4) + c]; }
        if (wi3 < NW_F4) { int kk = wi3 / 25, c = wi3 % 25; rw3 = W4[(size_t)(k0 + kk) * (HH/4) + c]; }
    }

    unsigned long long accP[4][2];
#pragma unroll
    for (int i = 0; i < 4; i++) { accP[i][0] = 0ull; accP[i][1] = 0ull; }

    int rg = tid / 25, cg = tid % 25;
    int rr = rg * 4,  cc = cg * 4;
    bool active = (tid < 200);

    for (int kc = 0; kc < KQ; kc += KC) {
        if (ai0 < NA_F4) { int r = ai0 >> 3, kf = (ai0 & 7) * 4;
            sA[kf+0][r] = ra0.x; sA[kf+1][r] = ra0.y; sA[kf+2][r] = ra0.z; sA[kf+3][r] = ra0.w; }
        if (ai1 < NA_F4) { int r = ai1 >> 3, kf = (ai1 & 7) * 4;
            sA[kf+0][r] = ra1.x; sA[kf+1][r] = ra1.y; sA[kf+2][r] = ra1.z; sA[kf+3][r] = ra1.w; }
        if (wi0 < NW_F4) { int kk = wi0 / 25, c = (wi0 % 25) * 4; *(float4*)&sW[kk][c] = rw0; }
        if (wi1 < NW_F4) { int kk = wi1 / 25, c = (wi1 % 25) * 4; *(float4*)&sW[kk][c] = rw1; }
        if (wi2 < NW_F4) { int kk = wi2 / 25, c = (wi2 % 25) * 4; *(float4*)&sW[kk][c] = rw2; }
        if (wi3 < NW_F4) { int kk = wi3 / 25, c = (wi3 % 25) * 4; *(float4*)&sW[kk][c] = rw3; }
        __syncthreads();

        int kn = kb + kc + KC;
        if (kc + KC < KQ) {
            if (ai0 < NA_F4) { int r = ai0 >> 3, kf = ai0 & 7; ra0 = A4[(size_t)(m0 + r) * (DD/4) + (kn>>2) + kf]; }
            if (ai1 < NA_F4) { int r = ai1 >> 3, kf = ai1 & 7; ra1 = A4[(size_t)(m0 + r) * (DD/4) + (kn>>2) + kf]; }
            if (wi0 < NW_F4) { int kk = wi0 / 25, c = wi0 % 25; rw0 = W4[(size_t)(kn + kk) * (HH/4) + c]; }
            if (wi1 < NW_F4) { int kk = wi1 / 25, c = wi1 % 25; rw1 = W4[(size_t)(kn + kk) * (HH/4) + c]; }
            if (wi2 < NW_F4) { int kk = wi2 / 25, c = wi2 % 25; rw2 = W4[(size_t)(kn + kk) * (HH/4) + c]; }
            if (wi3 < NW_F4) { int kk = wi3 / 25, c = wi3 % 25; rw3 = W4[(size_t)(kn + kk) * (HH/4) + c]; }
        }

        if (active) {
#pragma unroll
            for (int kk = 0; kk < KC; kk++) {
                float4 a = *(const float4*)&sA[kk][rr];
                float4 w = *(const float4*)&sW[kk][cc];
                const unsigned long long* wp = (const unsigned long long*)&w;
                float av[4] = {a.x, a.y, a.z, a.w};
#pragma unroll
                for (int i = 0; i < 4; i++) {
                    unsigned long long ad = f32x2_pack(av[i], av[i]);
                    f32x2_fma(accP[i][0], ad, wp[0]);
                    f32x2_fma(accP[i][1], ad, wp[1]);
                }
            }
        }
        __syncthreads();
    }

    if (active) {
#pragma unroll
        for (int i = 0; i < 4; i++) {
            float2 p0 = f32x2_unpack(accP[i][0]);
            float2 p1 = f32x2_unpack(accP[i][1]);
            size_t o = ((size_t)blockIdx.y * M_TOTAL + m0 + rr + i) * HH + cc;
            *(float4*)&g_part[o] = make_float4(p0.x, p0.y, p1.x, p1.y);
        }
    }
}

// ---------------- Kernel 4: combine 4 partials + bias + tanh -------------------
__global__ void __launch_bounds__(256) k_epi(const float* __restrict__ bias,
                                             float* __restrict__ out) {
    int i = blockIdx.x * 256 + threadIdx.x;       // float4 index, 102400 total
    if (i < M_TOTAL * HH / 4) {
        const float4* p = (const float4*)g_part;
        float4 a = p[i];
        float4 b = p[i + M_TOTAL * HH / 4];
        float4 c = p[i + 2 * (M_TOTAL * HH / 4)];
        float4 d = p[i + 3 * (M_TOTAL * HH / 4)];
        int cbase = (i * 4) % HH;                 // 100 % 4 == 0, no straddle
        float4 v;
        v.x = tanhf(a.x + b.x + c.x + d.x + bias[cbase + 0]);
        v.y = tanhf(a.y + b.y + c.y + d.y + bias[cbase + 1]);
        v.z = tanhf(a.z + b.z + c.z + d.z + bias[cbase + 2]);
        v.w = tanhf(a.w + b.w + c.w + d.w + bias[cbase + 3]);
        ((float4*)out)[i] = v;
    }
}

extern "C" void kernel_launch(void* const* d_in, const int* in_sizes, int n_in,
                              void* d_out, int out_size) {
    const float* seq   = (const float*)d_in[0];
    const int*   spans = (const int*)d_in[1];
    const int*   mask  = (const int*)d_in[2];
    const float* att_w = (const float*)d_in[3];
    const float* att_b = (const float*)d_in[4];
    const float* ffn_w = (const float*)d_in[5];
    const float* ffn_b = (const float*)d_in[6];
    float*       out   = (float*)d_out;

    k_logits<<<(BB * SS) / 32, 256>>>(seq, att_w, att_b);
    k_span<<<M_TOTAL, 192>>>(seq, spans, mask);
    k_gemm<<<dim3(128, KSPLIT), 224>>>(ffn_w);
    k_epi<<<(M_TOTAL * HH / 4 + 255) / 256, 256>>>(ffn_b, out);
}

// round 8
// speedup vs baseline: 1.0286x; 1.0286x over previous
#include <cuda_runtime.h>

#define BB 8
#define SS 2048
#define DD 768
#define NSP 512
#define MAXW 30
#define HH 100
#define M_TOTAL (BB*NSP)   /* 4096 */

__device__ float g_logits[BB*SS];
__device__ float g_att[(size_t)M_TOTAL*DD];

typedef unsigned long long ull;

__device__ __forceinline__ void f32x2_fma(ull& acc, ull a, ull b) {
    asm("fma.rn.f32x2 %0, %1, %2, %0;" : "+l"(acc) : "l"(a), "l"(b));
}
__device__ __forceinline__ ull f32x2_pack(float x, float y) {
    ull r;
    asm("mov.b64 %0, {%1, %2};" : "=l"(r) : "r"(__float_as_uint(x)), "r"(__float_as_uint(y)));
    return r;
}
__device__ __forceinline__ float2 f32x2_unpack(ull v) {
    unsigned int lo, hi;
    asm("mov.b64 {%0, %1}, %2;" : "=r"(lo), "=r"(hi) : "l"(v));
    return make_float2(__uint_as_float(lo), __uint_as_float(hi));
}

// ---------------- Kernel 1: logits, 4 rows/warp, f32x2, 2 staged batches -------
__global__ void __launch_bounds__(256, 2) k_logits(const float* __restrict__ seq,
                                                   const float* __restrict__ att_w,
                                                   const float* __restrict__ att_b) {
    __shared__ float sw[DD];
    int tid = threadIdx.x;
    for (int i = tid; i < DD; i += 256) sw[i] = att_w[i];
    __syncthreads();
    int warp = tid >> 5, lane = tid & 31;

    float4 wreg[6];
    const float4* w4 = (const float4*)sw;
#pragma unroll
    for (int j = 0; j < 6; j++) wreg[j] = w4[lane + 32 * j];

    int p0 = (blockIdx.x * 8 + warp) * 4;
    const float4* r0 = (const float4*)(seq + (size_t)(p0 + 0) * DD);
    const float4* r1 = (const float4*)(seq + (size_t)(p0 + 1) * DD);
    const float4* r2 = (const float4*)(seq + (size_t)(p0 + 2) * DD);
    const float4* r3 = (const float4*)(seq + (size_t)(p0 + 3) * DD);

    ull acc[4] = {0ull, 0ull, 0ull, 0ull};

#pragma unroll
    for (int s = 0; s < 2; s++) {
        float4 x[4][3];
#pragma unroll
        for (int j = 0; j < 3; j++) {
            int col = lane + 32 * (3 * s + j);
            x[0][j] = r0[col]; x[1][j] = r1[col]; x[2][j] = r2[col]; x[3][j] = r3[col];
        }
#pragma unroll
        for (int j = 0; j < 3; j++) {
            const ull* wp = (const ull*)&wreg[3 * s + j];
#pragma unroll
            for (int r = 0; r < 4; r++) {
                const ull* xp = (const ull*)&x[r][j];
                f32x2_fma(acc[r], xp[0], wp[0]);
                f32x2_fma(acc[r], xp[1], wp[1]);
            }
        }
    }

    float s0, s1, s2, s3;
    { float2 p = f32x2_unpack(acc[0]); s0 = p.x + p.y; }
    { float2 p = f32x2_unpack(acc[1]); s1 = p.x + p.y; }
    { float2 p = f32x2_unpack(acc[2]); s2 = p.x + p.y; }
    { float2 p = f32x2_unpack(acc[3]); s3 = p.x + p.y; }
#pragma unroll
    for (int o = 16; o > 0; o >>= 1) {
        s0 += __shfl_xor_sync(0xffffffffu, s0, o);
        s1 += __shfl_xor_sync(0xffffffffu, s1, o);
        s2 += __shfl_xor_sync(0xffffffffu, s2, o);
        s3 += __shfl_xor_sync(0xffffffffu, s3, o);
    }
    if (lane == 0) {
        float b = att_b[0];
        *(float4*)&g_logits[p0] = make_float4(s0 + b, s1 + b, s2 + b, s3 + b);
    }
}

// ---------------- Kernel 2: per-span softmax + weighted sum (seq L2-hot) -------
__global__ void k_span(const float* __restrict__ seq,
                       const int* __restrict__ spans,
                       const int* __restrict__ mask) {
    __shared__ float s_attn[MAXW];
    __shared__ int   s_start, s_cnt;
    int sp  = blockIdx.x;
    int b   = sp >> 9;
    int tid = threadIdx.x;

    if (tid < 32) {
        int start = spans[sp * 2];
        int cnt   = spans[sp * 2 + 1] - start;        // width 1..30
        float lg = (tid < cnt) ? g_logits[b * SS + start + tid] : -1e30f;
        float mx = lg;
#pragma unroll
        for (int o = 16; o > 0; o >>= 1) mx = fmaxf(mx, __shfl_xor_sync(0xffffffffu, mx, o));
        float ex = (tid < cnt) ? expf(lg - mx) : 0.f;
        float sm = ex;
#pragma unroll
        for (int o = 16; o > 0; o >>= 1) sm += __shfl_xor_sync(0xffffffffu, sm, o);
        float mk = (float)mask[sp];
        if (tid < MAXW) s_attn[tid] = ex / sm * mk;
        if (tid == 0) { s_start = start; s_cnt = cnt; }
    }
    __syncthreads();

    int start = s_start, cnt = s_cnt;
    const float4* base = (const float4*)seq + (size_t)(b * SS + start) * (DD / 4) + tid;
    float4 acc = make_float4(0.f, 0.f, 0.f, 0.f);
#pragma unroll 4
    for (int w = 0; w < cnt; w++) {
        float a  = s_attn[w];
        float4 v = base[(size_t)w * (DD / 4)];
        acc.x += a * v.x; acc.y += a * v.y; acc.z += a * v.z; acc.w += a * v.w;
    }
    ((float4*)g_att)[(size_t)sp * (DD / 4) + tid] = acc;
}

// -------- Kernel 3: GEMM + bias + tanh, broadcast-W, in-block split-K=2 --------
// grid = 128 (M-tile 32), block = 448 = 14 warps.
// Warp w: half = w/7 (K-half), wg = w%7 (16-col group). Lane: r = lane&15,
// cs = lane>>4. Thread owns rows {m0+r, m0+r+16} x cols [wg*16+cs*8, +8).
// Per kk: 2 scalar LDS (A, pair-broadcast) + 2 LDS.128 (W, warp-broadcast)
// + 2 packs + 8 FMA2 -> 32 MACs. Crossbar ~320B/warp-kk << fma time.
#define KC 32
#define NA_F4 ((32*KC)/4)    /* 256 */
#define NW_F4 ((KC*HH)/4)    /* 800 */

__global__ void __launch_bounds__(448) k_gemm(const float* __restrict__ W,
                                              const float* __restrict__ bias,
                                              float* __restrict__ out) {
    __shared__ float sA[KC][36];
    __shared__ float sW[KC][112];    // cols [100,112) zero-padded once
    __shared__ float sC[224][20];    // half-1 partials (16 used, f4-aligned stride)
    __shared__ float sB[HH];

    int m0   = blockIdx.x * 32;
    int tid  = threadIdx.x;
    int warp = tid >> 5, lane = tid & 31;
    int half = warp / 7;
    int wg   = warp % 7;
    int r    = lane & 15;
    int cs   = lane >> 4;
    int col  = wg * 16 + cs * 8;     // may reach 104; guarded at store

    if (tid < HH) sB[tid] = bias[tid];
    if (tid < 12 * KC) { int kk = tid / 12, c = 100 + tid % 12; sW[kk][c] = 0.f; }

    const float4* A4 = (const float4*)g_att;
    const float4* W4 = (const float4*)W;

    int aIdx  = tid;                 // <256: A f4 slot (row = aIdx>>3, kf4 = aIdx&7)
    int wIdx0 = tid, wIdx1 = tid + 448;   // <800: kk = idx/25, c4 = idx%25

    float4 ra, rw0, rw1;
    if (aIdx < NA_F4)  ra  = A4[(size_t)(m0 + (aIdx >> 3)) * (DD/4) + (aIdx & 7)];
    if (wIdx0 < NW_F4) rw0 = W4[(size_t)(wIdx0 / 25) * (HH/4) + wIdx0 % 25];
    if (wIdx1 < NW_F4) rw1 = W4[(size_t)(wIdx1 / 25) * (HH/4) + wIdx1 % 25];

    ull acc[8];
#pragma unroll
    for (int i = 0; i < 8; i++) acc[i] = 0ull;

    for (int kc = 0; kc < DD; kc += KC) {
        if (aIdx < NA_F4) { int row = aIdx >> 3, kf = (aIdx & 7) * 4;
            sA[kf+0][row] = ra.x; sA[kf+1][row] = ra.y;
            sA[kf+2][row] = ra.z; sA[kf+3][row] = ra.w; }
        if (wIdx0 < NW_F4) { int kk = wIdx0 / 25, c = (wIdx0 % 25) * 4; *(float4*)&sW[kk][c] = rw0; }
        if (wIdx1 < NW_F4) { int kk = wIdx1 / 25, c = (wIdx1 % 25) * 4; *(float4*)&sW[kk][c] = rw1; }
        __syncthreads();

        int kn = kc + KC;
        if (kn < DD) {
            if (aIdx < NA_F4)  ra  = A4[(size_t)(m0 + (aIdx >> 3)) * (DD/4) + (kn >> 2) + (aIdx & 7)];
            if (wIdx0 < NW_F4) rw0 = W4[(size_t)(kn + wIdx0 / 25) * (HH/4) + wIdx0 % 25];
            if (wIdx1 < NW_F4) rw1 = W4[(size_t)(kn + wIdx1 / 25) * (HH/4) + wIdx1 % 25];
        }

        int kbase = half * 16;
#pragma unroll
        for (int k2 = 0; k2 < 16; k2++) {
            int kk = kbase + k2;
            float a0 = sA[kk][r];
            float a1 = sA[kk][r + 16];
            float4 w0 = *(const float4*)&sW[kk][col];
            float4 w1 = *(const float4*)&sW[kk][col + 4];
            const ull* wp0 = (const ull*)&w0;
            const ull* wp1 = (const ull*)&w1;
            ull ad0 = f32x2_pack(a0, a0);
            ull ad1 = f32x2_pack(a1, a1);
            f32x2_fma(acc[0], ad0, wp0[0]);
            f32x2_fma(acc[1], ad0, wp0[1]);
            f32x2_fma(acc[2], ad0, wp1[0]);
            f32x2_fma(acc[3], ad0, wp1[1]);
            f32x2_fma(acc[4], ad1, wp0[0]);
            f32x2_fma(acc[5], ad1, wp0[1]);
            f32x2_fma(acc[6], ad1, wp1[0]);
            f32x2_fma(acc[7], ad1, wp1[1]);
        }
        __syncthreads();
    }

    // combine halves: half 1 dumps partials, half 0 finishes
    if (half == 1) {
        float* dst = &sC[tid - 224][0];
#pragma unroll
        for (int i = 0; i < 8; i++) {
            float2 p = f32x2_unpack(acc[i]);
            dst[i * 2] = p.x; dst[i * 2 + 1] = p.y;
        }
    }
    __syncthreads();

    if (half == 0) {
        const float* src = &sC[tid][0];
        float v[16];
#pragma unroll
        for (int i = 0; i < 8; i++) {
            float2 p = f32x2_unpack(acc[i]);
            v[i * 2] = p.x; v[i * 2 + 1] = p.y;
        }
#pragma unroll
        for (int rr = 0; rr < 2; rr++) {          // row 0: m0+r, row 1: m0+r+16
            size_t row = (size_t)(m0 + r + rr * 16);
            if (col < HH) {
                float4 o;
                o.x = tanhf(v[rr*8+0] + src[rr*8+0] + sB[col+0]);
                o.y = tanhf(v[rr*8+1] + src[rr*8+1] + sB[col+1]);
                o.z = tanhf(v[rr*8+2] + src[rr*8+2] + sB[col+2]);
                o.w = tanhf(v[rr*8+3] + src[rr*8+3] + sB[col+3]);
                *(float4*)&out[row * HH + col] = o;
            }
            if (col + 4 < HH) {
                float4 o;
                o.x = tanhf(v[rr*8+4] + src[rr*8+4] + sB[col+4]);
                o.y = tanhf(v[rr*8+5] + src[rr*8+5] + sB[col+5]);
                o.z = tanhf(v[rr*8+6] + src[rr*8+6] + sB[col+6]);
                o.w = tanhf(v[rr*8+7] + src[rr*8+7] + sB[col+7]);
                *(float4*)&out[row * HH + col + 4] = o;
            }
        }
    }
}

extern "C" void kernel_launch(void* const* d_in, const int* in_sizes, int n_in,
                              void* d_out, int out_size) {
    const float* seq   = (const float*)d_in[0];
    const int*   spans = (const int*)d_in[1];
    const int*   mask  = (const int*)d_in[2];
    const float* att_w = (const float*)d_in[3];
    const float* att_b = (const float*)d_in[4];
    const float* ffn_w = (const float*)d_in[5];
    const float* ffn_b = (const float*)d_in[6];
    float*       out   = (float*)d_out;

    k_logits<<<(BB * SS) / 32, 256>>>(seq, att_w, att_b);
    k_span<<<M_TOTAL, 192>>>(seq, spans, mask);
    k_gemm<<<128, 448>>>(ffn_w, ffn_b, out);
}

// round 9
// speedup vs baseline: 1.0910x; 1.0607x over previous
#include <cuda_runtime.h>
#include <cuda_pipeline.h>

#define BB 8
#define SS 2048
#define DD 768
#define NSP 512
#define MAXW 30
#define HH 100
#define M_TOTAL (BB*NSP)   /* 4096 */

__device__ float g_logits[BB*SS];
__device__ float g_att[(size_t)M_TOTAL*DD];

typedef unsigned long long ull;

__device__ __forceinline__ void f32x2_fma(ull& acc, ull a, ull b) {
    asm("fma.rn.f32x2 %0, %1, %2, %0;" : "+l"(acc) : "l"(a), "l"(b));
}
__device__ __forceinline__ ull f32x2_pack(float x, float y) {
    ull r;
    asm("mov.b64 %0, {%1, %2};" : "=l"(r) : "r"(__float_as_uint(x)), "r"(__float_as_uint(y)));
    return r;
}
__device__ __forceinline__ float2 f32x2_unpack(ull v) {
    unsigned int lo, hi;
    asm("mov.b64 {%0, %1}, %2;" : "=r"(lo), "=r"(hi) : "l"(v));
    return make_float2(__uint_as_float(lo), __uint_as_float(hi));
}

// -------- Kernel 1: logits via cp.async double-buffered streaming --------------
// grid = 512, block = 256. 32 rows/block, 4 stages x 8 rows (24KB), 2 buffers.
#define STG_ROWS 8
#define STG_F4   (STG_ROWS * (DD/4))   /* 1536 f4 per stage */

__global__ void __launch_bounds__(256) k_logits(const float* __restrict__ seq,
                                                const float* __restrict__ att_w,
                                                const float* __restrict__ att_b) {
    __shared__ float4 sbuf[2][STG_F4];     // 2 x 24KB = 48KB (static limit)

    int tid = threadIdx.x, warp = tid >> 5, lane = tid & 31;
    size_t base = (size_t)blockIdx.x * 32;
    const float4* src = (const float4*)seq + base * (DD / 4);

    // prefetch stages 0 and 1
#pragma unroll
    for (int k = 0; k < 6; k++) {
        int idx = tid + k * 256;
        __pipeline_memcpy_async(&sbuf[0][idx], &src[idx], 16);
    }
    __pipeline_commit();
#pragma unroll
    for (int k = 0; k < 6; k++) {
        int idx = tid + k * 256;
        __pipeline_memcpy_async(&sbuf[1][idx], &src[STG_F4 + idx], 16);
    }
    __pipeline_commit();

    // weights to registers (broadcast loads, L2/L1 cached)
    float4 wreg[6];
    const float4* w4 = (const float4*)att_w;
#pragma unroll
    for (int j = 0; j < 6; j++) wreg[j] = __ldg(&w4[lane + 32 * j]);
    float bconst = __ldg(att_b);

    for (int s = 0; s < 4; s++) {
        if (s < 3) __pipeline_wait_prior(1);
        else       __pipeline_wait_prior(0);
        __syncthreads();

        const float4* row = &sbuf[s & 1][warp * (DD / 4)];
        float4 x[6];
#pragma unroll
        for (int j = 0; j < 6; j++) x[j] = row[lane + 32 * j];
        ull acc = 0ull;
#pragma unroll
        for (int j = 0; j < 6; j++) {
            const ull* xp = (const ull*)&x[j];
            const ull* wp = (const ull*)&wreg[j];
            f32x2_fma(acc, xp[0], wp[0]);
            f32x2_fma(acc, xp[1], wp[1]);
        }
        float2 p = f32x2_unpack(acc);
        float sum = p.x + p.y;
#pragma unroll
        for (int o = 16; o > 0; o >>= 1) sum += __shfl_xor_sync(0xffffffffu, sum, o);
        if (lane == 0) g_logits[base + s * STG_ROWS + warp] = sum + bconst;
        __syncthreads();

        if (s + 2 < 4) {
            const float4* g = src + (size_t)(s + 2) * STG_F4;
#pragma unroll
            for (int k = 0; k < 6; k++) {
                int idx = tid + k * 256;
                __pipeline_memcpy_async(&sbuf[s & 1][idx], &g[idx], 16);
            }
            __pipeline_commit();
        }
    }
}

// ---------------- Kernel 2: per-span softmax + weighted sum (seq L2-hot) -------
__global__ void k_span(const float* __restrict__ seq,
                       const int* __restrict__ spans,
                       const int* __restrict__ mask) {
    __shared__ float s_attn[MAXW];
    __shared__ int   s_start, s_cnt;
    int sp  = blockIdx.x;
    int b   = sp >> 9;
    int tid = threadIdx.x;

    if (tid < 32) {
        int start = spans[sp * 2];
        int cnt   = spans[sp * 2 + 1] - start;        // width 1..30
        float lg = (tid < cnt) ? g_logits[b * SS + start + tid] : -1e30f;
        float mx = lg;
#pragma unroll
        for (int o = 16; o > 0; o >>= 1) mx = fmaxf(mx, __shfl_xor_sync(0xffffffffu, mx, o));
        float ex = (tid < cnt) ? expf(lg - mx) : 0.f;
        float sm = ex;
#pragma unroll
        for (int o = 16; o > 0; o >>= 1) sm += __shfl_xor_sync(0xffffffffu, sm, o);
        float mk = (float)mask[sp];
        if (tid < MAXW) s_attn[tid] = ex / sm * mk;
        if (tid == 0) { s_start = start; s_cnt = cnt; }
    }
    __syncthreads();

    int start = s_start, cnt = s_cnt;
    const float4* base = (const float4*)seq + (size_t)(b * SS + start) * (DD / 4) + tid;
    float4 acc = make_float4(0.f, 0.f, 0.f, 0.f);
#pragma unroll 4
    for (int w = 0; w < cnt; w++) {
        float a  = s_attn[w];
        float4 v = base[(size_t)w * (DD / 4)];
        acc.x += a * v.x; acc.y += a * v.y; acc.z += a * v.z; acc.w += a * v.w;
    }
    ((float4*)g_att)[(size_t)sp * (DD / 4) + tid] = acc;
}

// -------- Kernel 3: GEMM + bias + tanh, broadcast-W, in-block split-K=2 --------
#define KC 32
#define NA_F4 ((32*KC)/4)    /* 256 */
#define NW_F4 ((KC*HH)/4)    /* 800 */

__global__ void __launch_bounds__(448) k_gemm(const float* __restrict__ W,
                                              const float* __restrict__ bias,
                                              float* __restrict__ out) {
    __shared__ float sA[KC][36];
    __shared__ float sW[KC][112];    // cols [100,112) zero-padded once
    __shared__ float sC[224][20];    // half-1 partials
    __shared__ float sB[HH];

    int m0   = blockIdx.x * 32;
    int tid  = threadIdx.x;
    int warp = tid >> 5, lane = tid & 31;
    int half = warp / 7;
    int wg   = warp % 7;
    int r    = lane & 15;
    int cs   = lane >> 4;
    int col  = wg * 16 + cs * 8;

    if (tid < HH) sB[tid] = bias[tid];
    if (tid < 12 * KC) { int kk = tid / 12, c = 100 + tid % 12; sW[kk][c] = 0.f; }

    const float4* A4 = (const float4*)g_att;
    const float4* W4 = (const float4*)W;

    int aIdx  = tid;
    int wIdx0 = tid, wIdx1 = tid + 448;

    float4 ra, rw0, rw1;
    if (aIdx < NA_F4)  ra  = A4[(size_t)(m0 + (aIdx >> 3)) * (DD/4) + (aIdx & 7)];
    if (wIdx0 < NW_F4) rw0 = W4[(size_t)(wIdx0 / 25) * (HH/4) + wIdx0 % 25];
    if (wIdx1 < NW_F4) rw1 = W4[(size_t)(wIdx1 / 25) * (HH/4) + wIdx1 % 25];

    ull acc[8];
#pragma unroll
    for (int i = 0; i < 8; i++) acc[i] = 0ull;

    for (int kc = 0; kc < DD; kc += KC) {
        if (aIdx < NA_F4) { int row = aIdx >> 3, kf = (aIdx & 7) * 4;
            sA[kf+0][row] = ra.x; sA[kf+1][row] = ra.y;
            sA[kf+2][row] = ra.z; sA[kf+3][row] = ra.w; }
        if (wIdx0 < NW_F4) { int kk = wIdx0 / 25, c = (wIdx0 % 25) * 4; *(float4*)&sW[kk][c] = rw0; }
        if (wIdx1 < NW_F4) { int kk = wIdx1 / 25, c = (wIdx1 % 25) * 4; *(float4*)&sW[kk][c] = rw1; }
        __syncthreads();

        int kn = kc + KC;
        if (kn < DD) {
            if (aIdx < NA_F4)  ra  = A4[(size_t)(m0 + (aIdx >> 3)) * (DD/4) + (kn >> 2) + (aIdx & 7)];
            if (wIdx0 < NW_F4) rw0 = W4[(size_t)(kn + wIdx0 / 25) * (HH/4) + wIdx0 % 25];
            if (wIdx1 < NW_F4) rw1 = W4[(size_t)(kn + wIdx1 / 25) * (HH/4) + wIdx1 % 25];
        }

        int kbase = half * 16;
#pragma unroll
        for (int k2 = 0; k2 < 16; k2++) {
            int kk = kbase + k2;
            float a0 = sA[kk][r];
            float a1 = sA[kk][r + 16];
            float4 w0 = *(const float4*)&sW[kk][col];
            float4 w1 = *(const float4*)&sW[kk][col + 4];
            const ull* wp0 = (const ull*)&w0;
            const ull* wp1 = (const ull*)&w1;
            ull ad0 = f32x2_pack(a0, a0);
            ull ad1 = f32x2_pack(a1, a1);
            f32x2_fma(acc[0], ad0, wp0[0]);
            f32x2_fma(acc[1], ad0, wp0[1]);
            f32x2_fma(acc[2], ad0, wp1[0]);
            f32x2_fma(acc[3], ad0, wp1[1]);
            f32x2_fma(acc[4], ad1, wp0[0]);
            f32x2_fma(acc[5], ad1, wp0[1]);
            f32x2_fma(acc[6], ad1, wp1[0]);
            f32x2_fma(acc[7], ad1, wp1[1]);
        }
        __syncthreads();
    }

    if (half == 1) {
        float* dst = &sC[tid - 224][0];
#pragma unroll
        for (int i = 0; i < 8; i++) {
            float2 p = f32x2_unpack(acc[i]);
            dst[i * 2] = p.x; dst[i * 2 + 1] = p.y;
        }
    }
    __syncthreads();

    if (half == 0) {
        const float* src = &sC[tid][0];
        float v[16];
#pragma unroll
        for (int i = 0; i < 8; i++) {
            float2 p = f32x2_unpack(acc[i]);
            v[i * 2] = p.x; v[i * 2 + 1] = p.y;
        }
#pragma unroll
        for (int rr = 0; rr < 2; rr++) {
            size_t row = (size_t)(m0 + r + rr * 16);
            if (col < HH) {
                float4 o;
                o.x = tanhf(v[rr*8+0] + src[rr*8+0] + sB[col+0]);
                o.y = tanhf(v[rr*8+1] + src[rr*8+1] + sB[col+1]);
                o.z = tanhf(v[rr*8+2] + src[rr*8+2] + sB[col+2]);
                o.w = tanhf(v[rr*8+3] + src[rr*8+3] + sB[col+3]);
                *(float4*)&out[row * HH + col] = o;
            }
            if (col + 4 < HH) {
                float4 o;
                o.x = tanhf(v[rr*8+4] + src[rr*8+4] + sB[col+4]);
                o.y = tanhf(v[rr*8+5] + src[rr*8+5] + sB[col+5]);
                o.z = tanhf(v[rr*8+6] + src[rr*8+6] + sB[col+6]);
                o.w = tanhf(v[rr*8+7] + src[rr*8+7] + sB[col+7]);
                *(float4*)&out[row * HH + col + 4] = o;
            }
        }
    }
}

extern "C" void kernel_launch(void* const* d_in, const int* in_sizes, int n_in,
                              void* d_out, int out_size) {
    const float* seq   = (const float*)d_in[0];
    const int*   spans = (const int*)d_in[1];
    const int*   mask  = (const int*)d_in[2];
    const float* att_w = (const float*)d_in[3];
    const float* att_b = (const float*)d_in[4];
    const float* ffn_w = (const float*)d_in[5];
    const float* ffn_b = (const float*)d_in[6];
    float*       out   = (float*)d_out;

    k_logits<<<512, 256>>>(seq, att_w, att_b);
    k_span<<<M_TOTAL, 192>>>(seq, spans, mask);
    k_gemm<<<128, 448>>>(ffn_w, ffn_b, out);
}